// round 16
// baseline (speedup 1.0000x reference)
#include <cuda_runtime.h>
#include <cuda_fp16.h>
#include <cstdint>
#include <cstddef>

// ---------------- problem constants ----------------
#define BB   4
#define TT   2048
#define HIDD 2048
#define HH   16
#define DKK  128
#define DVV  128
#define NBT  (BB*TT)           // 8192 rows
static constexpr float SCALE_F = 0.08838834764831845f;  // 128^-0.5
static constexpr float EPS_F   = 1e-5f;

// ---------------- scratch (device globals; no allocation allowed) ----------------
#define BUFE ((size_t)NBT * HIDD)      // 16.78M elems
#define WE   ((size_t)HIDD * HIDD)     // 4.19M elems
__device__ float  g_scratch[BUFE * 9 + (size_t)NBT * HH];
__device__ __half g_hf[BUFE * 4 + WE * 6];

__device__ __forceinline__ float sigmoidf_(float x) { return 1.f / (1.f + expf(-x)); }

__device__ __forceinline__ uint32_t smem_u32(const void* p) {
    uint32_t a;
    asm("{ .reg .u64 t; cvta.to.shared.u64 t, %1; cvt.u32.u64 %0, t; }" : "=r"(a) : "l"(p));
    return a;
}
__device__ __forceinline__ void cp16(uint32_t dst, const void* src) {
    asm volatile("cp.async.cg.shared.global [%0], [%1], 16;" :: "r"(dst), "l"(src));
}
__device__ __forceinline__ void cp_commit() {
    asm volatile("cp.async.commit_group;" ::: "memory");
}
__device__ __forceinline__ void ldsm4(uint32_t* r, uint32_t addr) {
    asm volatile("ldmatrix.sync.aligned.m8n8.x4.shared.b16 {%0,%1,%2,%3}, [%4];"
                 : "=r"(r[0]), "=r"(r[1]), "=r"(r[2]), "=r"(r[3]) : "r"(addr));
}
__device__ __forceinline__ void mma16816h(float* c, const uint32_t* a, uint32_t b0, uint32_t b1) {
    asm volatile("mma.sync.aligned.m16n8k16.row.col.f32.f16.f16.f32 "
                 "{%0,%1,%2,%3}, {%4,%5,%6,%7}, {%8,%9}, {%0,%1,%2,%3};"
                 : "+f"(c[0]), "+f"(c[1]), "+f"(c[2]), "+f"(c[3])
                 : "r"(a[0]), "r"(a[1]), "r"(a[2]), "r"(a[3]), "r"(b0), "r"(b1));
}

// ---- packed f32x2 helpers ----
__device__ __forceinline__ uint64_t f32x2_fma(uint64_t a, uint64_t b, uint64_t c) {
    uint64_t d;
    asm("fma.rn.f32x2 %0, %1, %2, %3;" : "=l"(d) : "l"(a), "l"(b), "l"(c));
    return d;
}
__device__ __forceinline__ uint64_t f32x2_mul(uint64_t a, uint64_t b) {
    uint64_t d;
    asm("mul.rn.f32x2 %0, %1, %2;" : "=l"(d) : "l"(a), "l"(b));
    return d;
}
__device__ __forceinline__ uint64_t pack2(float x) {
    uint64_t d; uint32_t u = __float_as_uint(x);
    asm("mov.b64 %0, {%1, %1};" : "=l"(d) : "r"(u));
    return d;
}
__device__ __forceinline__ float unpack_sum(uint64_t p) {
    uint32_t lo, hi;
    asm("mov.b64 {%0, %1}, %2;" : "=r"(lo), "=r"(hi) : "l"(p));
    return __uint_as_float(lo) + __uint_as_float(hi);
}
__device__ __forceinline__ void ldg_v2u64(uint64_t& a, uint64_t& b, const void* p) {
    asm volatile("ld.global.v2.u64 {%0, %1}, [%2];" : "=l"(a), "=l"(b) : "l"(p));
}
__device__ __forceinline__ void prefetch_l2(const void* p) {
    asm volatile("prefetch.global.L2 [%0];" :: "l"(p));
}

// ======================================================================
// mma.sync GEMM, fp16x2 split: C = (Ah + Al) @ Bh^T.  (unchanged from R13)
// ======================================================================
#define GK     2048
#define BK     32
#define NCH    (GK / BK)          // 64
#define SM_A   0
#define SM_B   (16 * 1024)
#define STAGE  (32 * 1024)
#define NSTAGE 3
#define SMEM_GEMM (NSTAGE * STAGE)     // 98304

struct GemmBatch {
    const __half* bh[5];
    const float* bias[5];
    float* C[5];
    int epi[5];
};

__global__ void __launch_bounds__(256, 2)
gemm_fp16x2_kernel(const __half* __restrict__ Ahi, const __half* __restrict__ Alo,
                   GemmBatch gb)
{
    extern __shared__ __align__(1024) char sm[];
    const uint32_t smb = smem_u32(sm);

    const int z    = blockIdx.z;
    const int tid  = threadIdx.x;
    const int wid  = tid >> 5;
    const int lane = tid & 31;
    const int bm   = blockIdx.y * 128;
    const int bn   = blockIdx.x * 128;
    const int wm   = wid & 3;
    const int wn   = wid >> 2;

    const int lrow = tid >> 3;
    const int lseg = tid & 7;
    const bool hiTh = (lseg < 4);
    const uint32_t swz = (uint32_t)((lseg * 16) ^ ((lrow & 7) << 4));
    const uint32_t sw0 = (uint32_t)(lrow * 128) + swz;
    const size_t   gofs = (size_t)lrow * GK + (lseg & 3) * 8;

    const __half* Aptr = (hiTh ? Ahi : Alo) + (size_t)bm * GK + gofs;
    const __half* Bptr = gb.bh[z] + (size_t)bn * GK + gofs;

    const float* bias = gb.bias[z];
    float* C = gb.C[z];
    const int epi = gb.epi[z];

    uint32_t psbase = smb;
    auto prefetch = [&]() {
        const uint32_t pa = psbase + SM_A + sw0;
        const uint32_t pb = psbase + SM_B + sw0;
        #pragma unroll
        for (int i = 0; i < 4; i++) {
            cp16(pa + i * 4096, Aptr + (size_t)i * 32 * GK);
            if (hiTh) cp16(pb + i * 4096, Bptr + (size_t)i * 32 * GK);
        }
        cp_commit();
        Aptr += BK;  Bptr += BK;
        psbase += STAGE;
        if (psbase == smb + NSTAGE * STAGE) psbase = smb;
    };

    prefetch();
    prefetch();

    float acc[2][8][4];
    #pragma unroll
    for (int i = 0; i < 2; i++)
        #pragma unroll
        for (int j = 0; j < 8; j++)
            #pragma unroll
            for (int q = 0; q < 4; q++) acc[i][j][q] = 0.f;

    const int l16  = lane & 15;
    const uint32_t xorv  = (uint32_t)((lane & 7) << 4);
    const uint32_t chalf = (uint32_t)((lane >> 4) * 16);
    const uint32_t xh0 = (chalf)      ^ xorv;
    const uint32_t xh1 = (32 + chalf) ^ xorv;
    const uint32_t xl0 = (64 + chalf) ^ xorv;
    const uint32_t xl1 = (96 + chalf) ^ xorv;
    const uint32_t aBase = SM_A + (uint32_t)((wm * 32 + l16) << 7);
    const uint32_t bBase = SM_B + (uint32_t)((wn * 64 + l16) << 7);

    uint32_t sbase = smb;
    for (int c = 0; c < NCH; c++) {
        if (c + 1 < NCH) asm volatile("cp.async.wait_group 1;" ::: "memory");
        else             asm volatile("cp.async.wait_group 0;" ::: "memory");
        __syncthreads();
        if (c + 2 < NCH) prefetch();

        const uint32_t sA = sbase + aBase;
        const uint32_t sB = sbase + bBase;
        #pragma unroll
        for (int kk = 0; kk < 2; kk++) {
            const uint32_t xh = kk ? xh1 : xh0;
            const uint32_t xl = kk ? xl1 : xl0;
            const uint32_t sAh = sA + xh, sAl = sA + xl;
            const uint32_t sBh = sB + xh;
            uint32_t ah[2][4], al[2][4];
            ldsm4(ah[0], sAh);
            ldsm4(ah[1], sAh + 2048);
            ldsm4(al[0], sAl);
            ldsm4(al[1], sAl + 2048);
            #pragma unroll
            for (int nt = 0; nt < 4; nt++) {
                uint32_t bh4[4];
                ldsm4(bh4, sBh + nt * 2048);
                #pragma unroll
                for (int mt = 0; mt < 2; mt++) {
                    mma16816h(acc[mt][nt * 2],     ah[mt], bh4[0], bh4[2]);
                    mma16816h(acc[mt][nt * 2 + 1], ah[mt], bh4[1], bh4[3]);
                    mma16816h(acc[mt][nt * 2],     al[mt], bh4[0], bh4[2]);
                    mma16816h(acc[mt][nt * 2 + 1], al[mt], bh4[1], bh4[3]);
                }
            }
        }
        sbase += STAGE;
        if (sbase == smb + NSTAGE * STAGE) sbase = smb;
    }

    #pragma unroll
    for (int mt = 0; mt < 2; mt++) {
        const int r0 = bm + wm * 32 + mt * 16 + (lane >> 2);
        #pragma unroll
        for (int j = 0; j < 8; j++) {
            const int cc = bn + wn * 64 + j * 8 + (lane & 3) * 2;
            float v0 = acc[mt][j][0], v1 = acc[mt][j][1];
            float v2 = acc[mt][j][2], v3 = acc[mt][j][3];
            if (epi == 1) {
                const float b0 = bias ? bias[cc]     : 0.f;
                const float b1 = bias ? bias[cc + 1] : 0.f;
                v0 = sigmoidf_(v0 + b0); v1 = sigmoidf_(v1 + b1);
                v2 = sigmoidf_(v2 + b0); v3 = sigmoidf_(v3 + b1);
            }
            *(float2*)(C + (size_t)r0 * HIDD + cc)       = make_float2(v0, v1);
            *(float2*)(C + (size_t)(r0 + 8) * HIDD + cc) = make_float2(v2, v3);
        }
    }
}

// ======================================================================
// elementwise fp32 -> (fp16 hi, fp16 lo), 4 elems/thread
// ======================================================================
__global__ void split_kernel(const float* __restrict__ in,
                             __half* __restrict__ hi, __half* __restrict__ lo)
{
    const size_t i = ((size_t)blockIdx.x * blockDim.x + threadIdx.x) * 4;
    const float4 v = *(const float4*)(in + i);
    __half h[4], l[4];
    const float* vp = (const float*)&v;
    #pragma unroll
    for (int j = 0; j < 4; j++) {
        h[j] = __float2half_rn(vp[j]);
        l[j] = __float2half_rn(vp[j] - __half2float(h[j]));
    }
    *(__half2*)(hi + i)     = __half2(h[0], h[1]);
    *(__half2*)(hi + i + 2) = __half2(h[2], h[3]);
    *(__half2*)(lo + i)     = __half2(l[0], l[1]);
    *(__half2*)(lo + i + 2) = __half2(l[2], l[3]);
}

// ======================================================================
// all six W [K=2048, N=2048] f32 -> fp16(W^T) [N, K] in ONE launch
// ======================================================================
struct WSet {
    const float* src[6];
    __half* hi[6];
};
__global__ void transpose_half_all_kernel(WSet ws)
{
    __shared__ float tile[32][33];
    const int z  = blockIdx.z;
    const float* W = ws.src[z];
    __half* hi = ws.hi[z];
    const int tx = threadIdx.x, ty = threadIdx.y;     // (32, 8)
    const int x0 = blockIdx.x * 32, y0 = blockIdx.y * 32;
    #pragma unroll
    for (int j = 0; j < 32; j += 8)
        tile[ty + j][tx] = W[(size_t)(y0 + ty + j) * HIDD + x0 + tx];
    __syncthreads();
    #pragma unroll
    for (int j = 0; j < 32; j += 8) {
        const float v = tile[tx][ty + j];
        hi[(size_t)(x0 + ty + j) * HIDD + y0 + tx] = __float2half_rn(v);
    }
}

// ======================================================================
// beta = sigmoid(x @ Wb + bb)
// ======================================================================
__global__ void beta_kernel(const float* __restrict__ x, const float* __restrict__ Wb,
                            const float* __restrict__ bb, float* __restrict__ out)
{
    const int row = blockIdx.x * 16 + (threadIdx.x >> 4);
    const int col = threadIdx.x & 15;
    const float* xr = x + (size_t)row * HIDD;
    float acc = 0.f;
    for (int k = 0; k < HIDD; k += 4) {
        float4 xv = *(const float4*)(xr + k);
        acc += xv.x * Wb[(k + 0) * HH + col];
        acc += xv.y * Wb[(k + 1) * HH + col];
        acc += xv.z * Wb[(k + 2) * HH + col];
        acc += xv.w * Wb[(k + 3) * HH + col];
    }
    out[(size_t)row * HH + col] = sigmoidf_(acc + bb[col]);
}

// ======================================================================
// 3 causal depthwise convs (K=4) + bias + SiLU (+scale) in one launch
// ======================================================================
struct ConvSet {
    const float* u[3];
    const float* w[3];
    const float* b[3];
    float* y[3];
    float scale[3];
};
__global__ void conv_silu_all_kernel(ConvSet cs)
{
    const int z = blockIdx.z;
    const size_t e = ((size_t)blockIdx.x * blockDim.x + threadIdx.x) * 4;
    const int c = (int)(e & (HIDD - 1));
    const int t = (int)((e >> 11) & (TT - 1));
    const float* u = cs.u[z];
    const float* w = cs.w[z];
    float4 acc = *(const float4*)(cs.b[z] + c);
    const float4 w0 = *(const float4*)(w + (size_t)c * 4);
    const float4 w1 = *(const float4*)(w + (size_t)(c + 1) * 4);
    const float4 w2 = *(const float4*)(w + (size_t)(c + 2) * 4);
    const float4 w3 = *(const float4*)(w + (size_t)(c + 3) * 4);
    const float* w0p = (const float*)&w0;
    const float* w1p = (const float*)&w1;
    const float* w2p = (const float*)&w2;
    const float* w3p = (const float*)&w3;
    #pragma unroll
    for (int j = 0; j < 4; j++) {
        if (t - 3 + j >= 0) {
            const float4 u4 = *(const float4*)(u + e + (ptrdiff_t)(j - 3) * HIDD);
            acc.x += w0p[j] * u4.x;
            acc.y += w1p[j] * u4.y;
            acc.z += w2p[j] * u4.z;
            acc.w += w3p[j] * u4.w;
        }
    }
    const float s = cs.scale[z];
    acc.x = acc.x * sigmoidf_(acc.x) * s;
    acc.y = acc.y * sigmoidf_(acc.y) * s;
    acc.z = acc.z * sigmoidf_(acc.z) * s;
    acc.w = acc.w * sigmoidf_(acc.w) * s;
    *(float4*)(cs.y[z] + e) = acc;
}

// ======================================================================
// Delta-rule scan v2: barrier-free, warp-independent, register-resident.
// 128 blocks (b, h, v-half) x 256 threads = 8 warps; warp = 8 v-rows.
// lane: c = lane&3 (32-k chunk), vl = lane>>2 (v-row 0..7).
// Double-buffered register pipeline (loads for t+1 issued before compute
// of t) + prefetch.global.L2 at distance 4. No smem, no __syncthreads.
// Only cross-lane comms: quad shfl reductions for sk and op.
// ======================================================================
__global__ void __launch_bounds__(256, 1) scan_kernel(
    const float* __restrict__ q, const float* __restrict__ k,
    const float* __restrict__ v, const float* __restrict__ a,
    const float* __restrict__ beta, float* __restrict__ o)
{
    const int blk  = blockIdx.x;
    const int b    = blk >> 5;
    const int h    = (blk >> 1) & 15;
    const int half = blk & 1;

    const int tid  = threadIdx.x;
    const int wid  = tid >> 5;
    const int lane = tid & 31;
    const int c    = lane & 3;
    const int vl   = lane >> 2;
    const int vg   = half * 64 + wid * 8 + vl;

    const size_t baseQK = (size_t)b * TT * HIDD + h * DKK + c * 32;
    const size_t baseVA = (size_t)b * TT * HIDD + h * DVV + vg;

    const float* kp = k + baseQK;
    const float* qp = q + baseQK;
    const float* vp = v + baseVA;
    const float* ap = a + baseVA;
    const float* bp = beta + (size_t)b * TT * HH + h;
    float* op_out   = o + (size_t)b * TT * HIDD + h * DKK + vg;

    uint64_t s2[16];
    #pragma unroll
    for (int i = 0; i < 16; i++) s2[i] = 0ull;

    // double-buffered operand registers
    uint64_t K2[2][16], Q2[2][16];
    float    V[2], A[2], Bt[2];

    // load t = 0 into buffer 0
    #pragma unroll
    for (int j = 0; j < 8; j++) ldg_v2u64(K2[0][2 * j], K2[0][2 * j + 1], kp + j * 4);
    #pragma unroll
    for (int j = 0; j < 8; j++) ldg_v2u64(Q2[0][2 * j], Q2[0][2 * j + 1], qp + j * 4);
    V[0] = *vp; A[0] = *ap; Bt[0] = *bp;

    for (int tt = 0; tt < TT; tt += 2) {
        #pragma unroll
        for (int u = 0; u < 2; u++) {
            const int t   = tt + u;
            const int cur = u;
            const int nxt = u ^ 1;

            // issue loads for t+1 (registers; independent of compute below)
            if (t + 1 < TT) {
                const size_t off = (size_t)(t + 1) * HIDD;
                #pragma unroll
                for (int j = 0; j < 8; j++)
                    ldg_v2u64(K2[nxt][2 * j], K2[nxt][2 * j + 1], kp + off + j * 4);
                #pragma unroll
                for (int j = 0; j < 8; j++)
                    ldg_v2u64(Q2[nxt][2 * j], Q2[nxt][2 * j + 1], qp + off + j * 4);
                V[nxt]  = vp[off];
                A[nxt]  = ap[off];
                Bt[nxt] = bp[(size_t)(t + 1) * HH];
            }
            // L2 prefetch at distance 4 (k/q rows dominate traffic)
            if (t + 4 < TT) {
                const size_t poff = (size_t)(t + 4) * HIDD;
                prefetch_l2(kp + poff);
                prefetch_l2(qp + poff);
                prefetch_l2(vp + poff);
                prefetch_l2(ap + poff);
            }

            // sk = S . k  (4 chains of depth 4)
            uint64_t c0 = 0ull, c1 = 0ull, c2 = 0ull, c3 = 0ull;
            #pragma unroll
            for (int i = 0; i < 4; i++) {
                c0 = f32x2_fma(s2[i],      K2[cur][i],      c0);
                c1 = f32x2_fma(s2[4 + i],  K2[cur][4 + i],  c1);
                c2 = f32x2_fma(s2[8 + i],  K2[cur][8 + i],  c2);
                c3 = f32x2_fma(s2[12 + i], K2[cur][12 + i], c3);
            }
            float sk = (unpack_sum(c0) + unpack_sum(c1)) + (unpack_sum(c2) + unpack_sum(c3));
            sk += __shfl_xor_sync(0xffffffffu, sk, 1);
            sk += __shfl_xor_sync(0xffffffffu, sk, 2);

            const float d  = Bt[cur] * (sk - V[cur]);
            const uint64_t dn2 = pack2(-d);
            const uint64_t av2 = pack2(A[cur]);

            // state update + output (4 chains)
            uint64_t o0 = 0ull, o1 = 0ull, o2 = 0ull, o3 = 0ull;
            #pragma unroll
            for (int i = 0; i < 4; i++) {
                uint64_t n0 = f32x2_mul(dn2, K2[cur][i]);
                uint64_t n1 = f32x2_mul(dn2, K2[cur][4 + i]);
                uint64_t n2 = f32x2_mul(dn2, K2[cur][8 + i]);
                uint64_t n3 = f32x2_mul(dn2, K2[cur][12 + i]);
                s2[i]      = f32x2_fma(av2, s2[i],      n0);
                s2[4 + i]  = f32x2_fma(av2, s2[4 + i],  n1);
                s2[8 + i]  = f32x2_fma(av2, s2[8 + i],  n2);
                s2[12 + i] = f32x2_fma(av2, s2[12 + i], n3);
                o0 = f32x2_fma(s2[i],      Q2[cur][i],      o0);
                o1 = f32x2_fma(s2[4 + i],  Q2[cur][4 + i],  o1);
                o2 = f32x2_fma(s2[8 + i],  Q2[cur][8 + i],  o2);
                o3 = f32x2_fma(s2[12 + i], Q2[cur][12 + i], o3);
            }
            float op = (unpack_sum(o0) + unpack_sum(o1)) + (unpack_sum(o2) + unpack_sum(o3));
            op += __shfl_xor_sync(0xffffffffu, op, 1);
            op += __shfl_xor_sync(0xffffffffu, op, 2);
            if (c == 0)
                op_out[(size_t)t * HIDD] = op;
        }
    }
}

// ======================================================================
// LayerNorm over DV=128 + gate, output split to fp16 hi/lo (final GEMM A)
// ======================================================================
__global__ void ln_gate_kernel(const float* __restrict__ o, const float* __restrict__ g,
                               const float* __restrict__ lnw, const float* __restrict__ lnb,
                               __half* __restrict__ ghi, __half* __restrict__ glo)
{
    const int gw   = (int)(((size_t)blockIdx.x * blockDim.x + threadIdx.x) >> 5);
    const int lane = threadIdx.x & 31;
    const size_t base = (size_t)gw * 128 + lane * 4;
    float4 x = *(const float4*)(o + base);
    float s  = x.x + x.y + x.z + x.w;
    float ss = x.x * x.x + x.y * x.y + x.z * x.z + x.w * x.w;
    #pragma unroll
    for (int m = 16; m > 0; m >>= 1) {
        s  += __shfl_xor_sync(0xffffffffu, s,  m);
        ss += __shfl_xor_sync(0xffffffffu, ss, m);
    }
    const float mu  = s * (1.f / 128.f);
    const float var = ss * (1.f / 128.f) - mu * mu;
    const float inv = rsqrtf(var + EPS_F);
    const float4 wv = *(const float4*)(lnw + lane * 4);
    const float4 bv = *(const float4*)(lnb + lane * 4);
    const float4 gv = *(const float4*)(g + base);
    float r[4];
    r[0] = ((x.x - mu) * inv * wv.x + bv.x) * gv.x;
    r[1] = ((x.y - mu) * inv * wv.y + bv.y) * gv.y;
    r[2] = ((x.z - mu) * inv * wv.z + bv.z) * gv.z;
    r[3] = ((x.w - mu) * inv * wv.w + bv.w) * gv.w;
    __half h[4], l[4];
    #pragma unroll
    for (int i = 0; i < 4; i++) {
        h[i] = __float2half_rn(r[i]);
        l[i] = __float2half_rn(r[i] - __half2float(h[i]));
    }
    *(__half2*)(ghi + base)     = __half2(h[0], h[1]);
    *(__half2*)(ghi + base + 2) = __half2(h[2], h[3]);
    *(__half2*)(glo + base)     = __half2(l[0], l[1]);
    *(__half2*)(glo + base + 2) = __half2(l[2], l[3]);
}

// ======================================================================
// launch
// ======================================================================
extern "C" void kernel_launch(void* const* d_in, const int* in_sizes, int n_in,
                              void* d_out, int out_size)
{
    const float* x       = (const float*)d_in[0];
    const float* Wq      = (const float*)d_in[1];
    const float* Wk      = (const float*)d_in[2];
    const float* Wv      = (const float*)d_in[3];
    const float* Wa      = (const float*)d_in[4];
    const float* ba      = (const float*)d_in[5];
    const float* Wb      = (const float*)d_in[6];
    const float* bb      = (const float*)d_in[7];
    const float* Wg      = (const float*)d_in[8];
    const float* Wo      = (const float*)d_in[9];
    const float* qconv_w = (const float*)d_in[10];
    const float* qconv_b = (const float*)d_in[11];
    const float* kconv_w = (const float*)d_in[12];
    const float* kconv_b = (const float*)d_in[13];
    const float* vconv_w = (const float*)d_in[14];
    const float* vconv_b = (const float*)d_in[15];
    const float* ln_w    = (const float*)d_in[16];
    const float* ln_b    = (const float*)d_in[17];

    void* sp = nullptr;
    cudaGetSymbolAddress(&sp, g_scratch);
    float* fb = (float*)sp;
    float* d_qpre = fb + 0 * BUFE;
    float* d_kpre = fb + 1 * BUFE;
    float* d_vpre = fb + 2 * BUFE;
    float* d_q    = fb + 3 * BUFE;
    float* d_k    = fb + 4 * BUFE;
    float* d_v    = fb + 5 * BUFE;
    float* d_a    = fb + 6 * BUFE;
    float* d_g    = fb + 7 * BUFE;
    float* d_o    = fb + 8 * BUFE;
    float* d_beta = fb + 9 * BUFE;

    void* bp = nullptr;
    cudaGetSymbolAddress(&bp, g_hf);
    __half* hb = (__half*)bp;
    __half* xhi = hb + 0 * BUFE;
    __half* xlo = hb + 1 * BUFE;
    __half* ghi = hb + 2 * BUFE;
    __half* glo = hb + 3 * BUFE;
    __half* wt  = hb + 4 * BUFE;              // 6 x WE: fp16(W^T) per weight
    __half* Wq_h = wt + 0 * WE;
    __half* Wk_h = wt + 1 * WE;
    __half* Wv_h = wt + 2 * WE;
    __half* Wa_h = wt + 3 * WE;
    __half* Wg_h = wt + 4 * WE;
    __half* Wo_h = wt + 5 * WE;

    cudaFuncSetAttribute(gemm_fp16x2_kernel,
                         cudaFuncAttributeMaxDynamicSharedMemorySize, SMEM_GEMM);

    // (1) split x
    split_kernel<<<(int)(BUFE / 4 / 256), 256>>>(x, xhi, xlo);

    // (2) all weight transposes (fp16)
    WSet ws;
    ws.src[0] = Wq; ws.hi[0] = Wq_h;
    ws.src[1] = Wk; ws.hi[1] = Wk_h;
    ws.src[2] = Wv; ws.hi[2] = Wv_h;
    ws.src[3] = Wa; ws.hi[3] = Wa_h;
    ws.src[4] = Wg; ws.hi[4] = Wg_h;
    ws.src[5] = Wo; ws.hi[5] = Wo_h;
    transpose_half_all_kernel<<<dim3(HIDD / 32, HIDD / 32, 6), dim3(32, 8)>>>(ws);

    // (3) beta
    beta_kernel<<<NBT / 16, 256>>>(x, Wb, bb, d_beta);

    // (4) 5 projections, one batched launch
    GemmBatch gb;
    gb.bh[0] = Wq_h; gb.bias[0] = nullptr; gb.C[0] = d_qpre; gb.epi[0] = 0;
    gb.bh[1] = Wk_h; gb.bias[1] = nullptr; gb.C[1] = d_kpre; gb.epi[1] = 0;
    gb.bh[2] = Wv_h; gb.bias[2] = nullptr; gb.C[2] = d_vpre; gb.epi[2] = 0;
    gb.bh[3] = Wa_h; gb.bias[3] = ba;      gb.C[3] = d_a;    gb.epi[3] = 1;
    gb.bh[4] = Wg_h; gb.bias[4] = nullptr; gb.C[4] = d_g;    gb.epi[4] = 1;
    gemm_fp16x2_kernel<<<dim3(HIDD / 128, NBT / 128, 5), 256, SMEM_GEMM>>>(xhi, xlo, gb);

    // (5) 3 convs, one batched launch
    ConvSet cs;
    cs.u[0] = d_qpre; cs.w[0] = qconv_w; cs.b[0] = qconv_b; cs.y[0] = d_q; cs.scale[0] = 1.f;
    cs.u[1] = d_kpre; cs.w[1] = kconv_w; cs.b[1] = kconv_b; cs.y[1] = d_k; cs.scale[1] = SCALE_F;
    cs.u[2] = d_vpre; cs.w[2] = vconv_w; cs.b[2] = vconv_b; cs.y[2] = d_v; cs.scale[2] = 1.f;
    conv_silu_all_kernel<<<dim3((int)((size_t)NBT * HIDD / 4 / 256), 1, 3), 256>>>(cs);

    // (6) scan (barrier-free v2)
    scan_kernel<<<BB * HH * 2, 256>>>(d_q, d_k, d_v, d_a, d_beta, d_o);

    // (7) LN + gate
    ln_gate_kernel<<<(NBT * HH) / 8, 256>>>(d_o, d_g, ln_w, ln_b, ghi, glo);

    // (8) output GEMM
    GemmBatch gbo = {};
    gbo.bh[0] = Wo_h; gbo.bias[0] = nullptr;
    gbo.C[0] = (float*)d_out; gbo.epi[0] = 0;
    gemm_fp16x2_kernel<<<dim3(HIDD / 128, NBT / 128, 1), 256, SMEM_GEMM>>>(ghi, glo, gbo);

    (void)in_sizes; (void)n_in; (void)out_size;
}